// round 12
// baseline (speedup 1.0000x reference)
#include <cuda_runtime.h>
#include <cstdint>

// Inverse 2D Haar DWT, output-centric decomposition.
//
// Inputs: 4 x (4,64,256,256) fp32.  Output: (4,64,512,512) fp32.
//
// One thread handles one float2 (2 consecutive cols j, j+1) from each band
// and writes two float4s:
//   even output row 2h : {a_j, b_j, a_{j+1}, b_{j+1}}
//   odd  output row 2h+1: {c_j, d_j, c_{j+1}, d_{j+1}}
//
// Warp-wide, loads are 32 x 8B contiguous (2 full 128B sectors / LDG.64) and
// stores are 32 x 16B contiguous (4 full sectors / STG.128) -> zero
// partial-sector wavefronts.
//
// Change this round (R12): stores use the DEFAULT cache policy instead of
// .cs (evict-first). Theory: with 126MB L2, default-policy dirty lines
// accumulate and drain in longer same-direction DRAM bursts, reducing
// read/write bus-turnaround frequency — the identified binding constraint
// (DRAM-active pinned at ~81.5% across all kernel shapes). Loads keep .cs
// (zero reuse; avoid polluting the dirty-line pool).
//
// Plateau so far: block=128, LDG.64 + STG.128, 1 unit/thread:
// kernel 74.3-74.9us, DRAM 81.4-82.0%. All structural axes swept (R2-R8).

static constexpr int W2_IN  = 256 / 2;        // 128 float2 per input row
static constexpr int H_IN   = 256;
static constexpr int W4_OUT = 512 / 4;        // 128 float4 per output row
static constexpr int PLANE_OUT_F4 = 512 * 512 / 4;  // 65536

__global__ __launch_bounds__(128)
void haar_idwt2_kernel(const float2* __restrict__ ll,
                       const float2* __restrict__ lh,
                       const float2* __restrict__ hl,
                       const float2* __restrict__ hh,
                       float4* __restrict__ out,
                       int n_f2)  // total float2 count = 4*64*256*128
{
    int f = blockIdx.x * blockDim.x + threadIdx.x;
    if (f >= n_f2) return;

    // Index math first: store addresses ready before loads complete.
    int col2  = f & (W2_IN - 1);     // f % 128
    int r     = f >> 7;
    int h     = r & (H_IN - 1);      // r % 256
    int plane = r >> 8;
    int idx0 = plane * PLANE_OUT_F4 + (2 * h) * W4_OUT + col2;  // even row
    int idx1 = idx0 + W4_OUT;                                   // odd row

    float2 vll = __ldcs(&ll[f]);
    float2 vlh = __ldcs(&lh[f]);
    float2 vhl = __ldcs(&hl[f]);
    float2 vhh = __ldcs(&hh[f]);

    float a0 = (vll.x + vlh.x + vhl.x + vhh.x) * 0.5f;
    float b0 = (vll.x + vlh.x - vhl.x - vhh.x) * 0.5f;
    float c0 = (vll.x - vlh.x + vhl.x - vhh.x) * 0.5f;
    float d0 = (vll.x - vlh.x - vhl.x + vhh.x) * 0.5f;

    float a1 = (vll.y + vlh.y + vhl.y + vhh.y) * 0.5f;
    float b1 = (vll.y + vlh.y - vhl.y - vhh.y) * 0.5f;
    float c1 = (vll.y - vlh.y + vhl.y - vhh.y) * 0.5f;
    float d1 = (vll.y - vlh.y - vhl.y + vhh.y) * 0.5f;

    // Default-policy stores (no .cs): let L2 batch dirty-line drains.
    out[idx0] = make_float4(a0, b0, a1, b1);
    out[idx1] = make_float4(c0, d0, c1, d1);
}

extern "C" void kernel_launch(void* const* d_in, const int* in_sizes, int n_in,
                              void* d_out, int out_size)
{
    const float2* ll = (const float2*)d_in[0];
    const float2* lh = (const float2*)d_in[1];
    const float2* hl = (const float2*)d_in[2];
    const float2* hh = (const float2*)d_in[3];
    float4* out = (float4*)d_out;

    int n_f2 = in_sizes[0] / 2;       // 8,388,608
    int threads = 128;
    int blocks = (n_f2 + threads - 1) / threads;

    haar_idwt2_kernel<<<blocks, threads>>>(ll, lh, hl, hh, out, n_f2);
}

// round 13
// speedup vs baseline: 1.0247x; 1.0247x over previous
#include <cuda_runtime.h>
#include <cstdint>

// Inverse 2D Haar DWT, output-centric decomposition — CONVERGED FINAL.
//
// Inputs: 4 x (4,64,256,256) fp32.  Output: (4,64,512,512) fp32.
//
// One thread handles one float2 (2 consecutive cols j, j+1) from each band
// and writes two float4s:
//   even output row 2h : {a_j, b_j, a_{j+1}, b_{j+1}}
//   odd  output row 2h+1: {c_j, d_j, c_{j+1}, d_{j+1}}
//
// Warp-wide, loads are 32 x 8B contiguous (2 full 128B sectors / LDG.64) and
// stores are 32 x 16B contiguous (4 full sectors / STG.128) -> zero
// partial-sector wavefronts. Streaming hints (.cs), zero reuse.
//
// Full GB300 exploration matrix (R2-R12), all measured:
//   load/store width: 8B-ld+16B-st best; 32B stores (R3) -10% DRAM-eff
//   units/thread:     1 best; 2-unit MLP (R4) neutral-worse
//   scheduling:       classic best; persistent grid-stride (R5) -10%
//   block size:       128 best (occ 88%); 256 -> 80%, 64 -> 68% (CTA-repl bound)
//   store policy:     .cs == default (R12) — L2 drain scheduling identical
// Plateau: kernel 74.3-74.9us, DRAM-active 81.1-82.0%, 6.45-6.5 TB/s on
// 537 MB irreducible traffic. Binding constraint is HBM read/write bus
// turnaround on the 50/50 mixed stream — a memory-controller property,
// invariant to every kernel-side shape. This is the hardware floor.

static constexpr int W2_IN  = 256 / 2;        // 128 float2 per input row
static constexpr int H_IN   = 256;
static constexpr int W4_OUT = 512 / 4;        // 128 float4 per output row
static constexpr int PLANE_OUT_F4 = 512 * 512 / 4;  // 65536

__global__ __launch_bounds__(128)
void haar_idwt2_kernel(const float2* __restrict__ ll,
                       const float2* __restrict__ lh,
                       const float2* __restrict__ hl,
                       const float2* __restrict__ hh,
                       float4* __restrict__ out,
                       int n_f2)  // total float2 count = 4*64*256*128
{
    int f = blockIdx.x * blockDim.x + threadIdx.x;
    if (f >= n_f2) return;

    // Index math first: store addresses ready before loads complete.
    int col2  = f & (W2_IN - 1);     // f % 128
    int r     = f >> 7;
    int h     = r & (H_IN - 1);      // r % 256
    int plane = r >> 8;
    int idx0 = plane * PLANE_OUT_F4 + (2 * h) * W4_OUT + col2;  // even row
    int idx1 = idx0 + W4_OUT;                                   // odd row

    float2 vll = __ldcs(&ll[f]);
    float2 vlh = __ldcs(&lh[f]);
    float2 vhl = __ldcs(&hl[f]);
    float2 vhh = __ldcs(&hh[f]);

    float a0 = (vll.x + vlh.x + vhl.x + vhh.x) * 0.5f;
    float b0 = (vll.x + vlh.x - vhl.x - vhh.x) * 0.5f;
    float c0 = (vll.x - vlh.x + vhl.x - vhh.x) * 0.5f;
    float d0 = (vll.x - vlh.x - vhl.x + vhh.x) * 0.5f;

    float a1 = (vll.y + vlh.y + vhl.y + vhh.y) * 0.5f;
    float b1 = (vll.y + vlh.y - vhl.y - vhh.y) * 0.5f;
    float c1 = (vll.y - vlh.y + vhl.y - vhh.y) * 0.5f;
    float d1 = (vll.y - vlh.y - vhl.y + vhh.y) * 0.5f;

    __stcs(&out[idx0], make_float4(a0, b0, a1, b1));
    __stcs(&out[idx1], make_float4(c0, d0, c1, d1));
}

extern "C" void kernel_launch(void* const* d_in, const int* in_sizes, int n_in,
                              void* d_out, int out_size)
{
    const float2* ll = (const float2*)d_in[0];
    const float2* lh = (const float2*)d_in[1];
    const float2* hl = (const float2*)d_in[2];
    const float2* hh = (const float2*)d_in[3];
    float4* out = (float4*)d_out;

    int n_f2 = in_sizes[0] / 2;       // 8,388,608
    int threads = 128;
    int blocks = (n_f2 + threads - 1) / threads;

    haar_idwt2_kernel<<<blocks, threads>>>(ll, lh, hl, hh, out, n_f2);
}